// round 12
// baseline (speedup 1.0000x reference)
#include <cuda_runtime.h>
#include <cuda_bf16.h>

#define T_Q 4096
#define L_KV 4096
#define LPAD (L_KV + 32)
#define NQB 64
#define NCHUNK 4

typedef unsigned long long ull;

// ---------------- scratch ----------------
__device__ float g_V[2][LPAD][128];
__device__ float g_kraw[2][LPAD];
__device__ float g_alpha[2][T_Q];
__device__ float g_beta[2][T_Q];
__device__ int   g_a[2][T_Q];
__device__ int   g_e[2][T_Q];
__device__ int   g_nc[2][T_Q];
__device__ float g_pacc[NCHUNK][2][T_Q][128];
__device__ float g_pden[NCHUNK][2][T_Q];
__device__ int   g_cnt[2][64];

// ---------------- helpers ----------------
__device__ __forceinline__ ull d_pk2(float a) {
    ull r; asm("mov.b64 %0, {%1, %1};" : "=l"(r) : "f"(a)); return r;
}
__device__ __forceinline__ ull d_fma2(ull a, ull b, ull c) {
    ull d; asm("fma.rn.f32x2 %0, %1, %2, %3;" : "=l"(d) : "l"(a), "l"(b), "l"(c)); return d;
}
__device__ __forceinline__ float2 d_up(ull v) {
    float2 f; asm("mov.b64 {%0, %1}, %2;" : "=f"(f.x), "=f"(f.y) : "l"(v)); return f;
}
__device__ __forceinline__ unsigned d_su32(const void* p) {
    unsigned r;
    asm("{ .reg .u64 t; cvta.to.shared.u64 t, %1; cvt.u32.u64 %0, t; }" : "=r"(r) : "l"(p));
    return r;
}

// ---------------- templated vproj core: 32 rows/CTA, warp owns 2 rows ----------------
template<int K, int SST>
__device__ __forceinline__ void vproj_core(const float* __restrict__ sm, int tid, int m, int rb,
                                           const float* __restrict__ Wv, const float* __restrict__ bv)
{
    int w = tid >> 5, lane = tid & 31;
    const ulonglong2* Wvp = (const ulonglong2*)Wv;
    float4 bias = ((const float4*)bv)[lane];
    const float* rbase = sm + (w * 2) * SST;

    ull a00 = 0ull, a01 = 0ull, a10 = 0ull, a11 = 0ull;

    #pragma unroll 8
    for (int i4 = 0; i4 < K / 4; i4++) {
        float4 r0 = *(const float4*)(rbase + i4 * 4);
        float4 r1 = *(const float4*)(rbase + SST + i4 * 4);
        #pragma unroll
        for (int ii = 0; ii < 4; ii++) {
            ulonglong2 wv = Wvp[(i4 * 4 + ii) * 32 + lane];
            float s0 = (ii == 0) ? r0.x : (ii == 1) ? r0.y : (ii == 2) ? r0.z : r0.w;
            float s1 = (ii == 0) ? r1.x : (ii == 1) ? r1.y : (ii == 2) ? r1.z : r1.w;
            ull p0 = d_pk2(s0), p1 = d_pk2(s1);
            a00 = d_fma2(p0, wv.x, a00); a01 = d_fma2(p0, wv.y, a01);
            a10 = d_fma2(p1, wv.x, a10); a11 = d_fma2(p1, wv.y, a11);
        }
    }

    int r0i = rb * 32 + w * 2;
    {
        float2 lo = d_up(a00), hi = d_up(a01);
        ((float4*)g_V[m][r0i])[lane] =
            make_float4(lo.x + bias.x, lo.y + bias.y, hi.x + bias.z, hi.y + bias.w);
    }
    {
        float2 lo = d_up(a10), hi = d_up(a11);
        ((float4*)g_V[m][r0i + 1])[lane] =
            make_float4(lo.x + bias.x, lo.y + bias.y, hi.x + bias.z, hi.y + bias.w);
    }
    if (lane < 2) g_kraw[m][r0i + lane] = sm[(w * 2 + lane) * SST + (K + 2) - 1];
}

// ---------------- kernel 1: qparams + vproj, 512-thread CTAs (unchanged, proven) ----------------
__global__ void __launch_bounds__(512) k_pre(
    const float* __restrict__ ref_data, const float* __restrict__ ref_time,
    const int* __restrict__ ref_idx,
    const float* __restrict__ m1_data, const float* __restrict__ m1_time, const int* __restrict__ m1_idx,
    const float* __restrict__ m2_data, const float* __restrict__ m2_time, const int* __restrict__ m2_idx,
    const float* __restrict__ Wq, const float* __restrict__ bq,
    const float* __restrict__ Wk1, const float* __restrict__ bk1,
    const float* __restrict__ Wv1, const float* __restrict__ bv1,
    const float* __restrict__ Wk2, const float* __restrict__ bk2,
    const float* __restrict__ Wv2, const float* __restrict__ bv2)
{
    __shared__ __align__(16) float sm[4448];     // 17.8 KB, unioned
    int b = blockIdx.x;
    int tid = threadIdx.x;
    int warp = tid >> 5, lane = tid & 31;

    if (b < NQB) {
        // ---- qab path ----
        float* rbuf = sm;                 // [64][65]
        float* swA  = sm + 4160;          // [2][64]
        float* swB  = swA + 128;          // [2][64]
        float* scAB = swB + 128;          // [4]
        int*   slb  = (int*)(scAB + 4);   // [2][9]

        int t0 = b * 64;
        for (int i = tid; i < 64 * 64; i += 512) {
            int row = i >> 6, col = i & 63;
            rbuf[row * 65 + col] = ref_data[t0 * 64 + i];
        }

        #pragma unroll
        for (int oo = 0; oo < 8; oo++) {
            int o = warp * 8 + oo;        // 0..127
            int m = o >> 6, j = o & 63;
            const float* Wk = m ? Wk2 : Wk1;
            const float* bk = m ? bk2 : bk1;
            const float* wqrow = Wq + j * 128;
            float aA = 0.f, aB = 0.f;
            #pragma unroll
            for (int kk = 0; kk < 4; kk++) {
                int i = lane + 32 * kk;
                if (i < 127) {
                    float w = __ldg(wqrow + i + 1);
                    aA += w * __ldg(bk + i);
                    aB += w * __ldg(Wk + i);
                }
            }
            #pragma unroll
            for (int off = 16; off; off >>= 1) {
                aA += __shfl_xor_sync(0xffffffffu, aA, off);
                aB += __shfl_xor_sync(0xffffffffu, aB, off);
            }
            if (lane == 0) {
                swA[m * 64 + j] = __ldg(wqrow) - aA;
                swB[m * 64 + j] = aB;
            }
        }
        if (warp < 4) {
            int m = warp & 1; bool isB = warp >= 2;
            const float* Wk = m ? Wk2 : Wk1;
            const float* bk = m ? bk2 : bk1;
            const float* vec = isB ? Wk : bk;
            float acc = 0.f;
            #pragma unroll
            for (int kk = 0; kk < 4; kk++) {
                int i = lane + 32 * kk;
                if (i < 127) acc += __ldg(bq + i + 1) * __ldg(vec + i);
            }
            #pragma unroll
            for (int off = 16; off; off >>= 1)
                acc += __shfl_xor_sync(0xffffffffu, acc, off);
            if (lane == 0)
                scAB[warp] = isB ? (acc + __ldg(Wk + 127)) : (__ldg(bq) - acc - __ldg(bk + 127));
        }
        if (warp == 15 && lane < 18) {
            int m = lane / 9, g = lane % 9;
            const int* midx = m ? m2_idx : m1_idx;
            int lo = 0, hi = L_KV;
            while (lo < hi) {
                int md = (lo + hi) >> 1;
                if (midx[md] < g) lo = md + 1; else hi = md;
            }
            slb[m * 9 + g] = lo;
        }
        __syncthreads();

        if (tid < 128) {
            int m = tid >> 6, q = tid & 63;
            int t = t0 + q;
            float dA = 0.f, dB = 0.f;
            #pragma unroll 8
            for (int i = 0; i < 64; i++) {
                float r = rbuf[q * 65 + i];
                dA += r * swA[m * 64 + i];
                dB += r * swB[m * 64 + i];
            }
            g_alpha[m][t] = dA + scAB[m];
            g_beta[m][t]  = dB + scAB[2 + m];

            int id = ref_idx[t];
            float qt = ref_time[t];
            const float* mt = m ? m2_time : m1_time;
            int lo = 0, hi = L_KV;
            while (lo < hi) {
                int md = (lo + hi) >> 1;
                if (mt[md] <= qt) lo = md + 1; else hi = md;
            }
            int a = slb[m * 9 + id], bb = slb[m * 9 + id + 1];
            if (a == bb) { a = 0; bb = L_KV; }
            int e = min(bb, max(lo, a));
            g_a[m][t] = a; g_e[m][t] = e; g_nc[m][t] = bb - e;
        }
        return;
    }

    // ---- vproj path: 32 rows per CTA, 16 warps ----
    int vb = b - NQB;            // 0..255
    int m = vb >> 7;
    int rb = vb & 127;
    int stride = m ? 66 : 130;
    int SST    = m ? 68 : 132;
    const float* src = (m ? m2_data : m1_data) + rb * 32 * stride;

    for (int r = warp; r < 32; r += 16)
        for (int c = lane; c < stride; c += 32)
            sm[r * SST + c] = src[r * stride + c];

    if (vb == 0) {
        float* gv = &g_V[0][0][0];
        for (int i = tid; i < 2 * 32 * 128; i += 512) {
            int mm = i / (32 * 128);
            int r  = i - mm * 32 * 128;
            gv[(mm * LPAD + L_KV) * 128 + r] = 0.f;
        }
        if (tid < 64) g_kraw[tid >> 5][L_KV + (tid & 31)] = 0.f;
        if (tid < 128) ((int*)g_cnt)[tid] = 0;
    }
    __syncthreads();

    if (m == 0) vproj_core<128, 132>(sm, tid, 0, rb, Wv1, bv1);
    else        vproj_core<64,  68>(sm, tid, 1, rb, Wv2, bv2);
}

// ---------------- kernel 2: attention, 8 warps x 8 queries (64 q/CTA), NCHUNK=4 ----------------
__global__ void __launch_bounds__(256) k_attn(const float* __restrict__ lt1,
                                              const float* __restrict__ lt2,
                                              float* __restrict__ out)
{
    int m = blockIdx.y, ch = blockIdx.z;
    int c = blockIdx.x;                              // 0..63
    int qb = (c & 1) ? (63 - (c >> 1)) : (c >> 1);   // front/back pairing for balance
    int tid = threadIdx.x;
    int warp = tid >> 5, lane = tid & 31;
    int t0c = qb * 64;

    __shared__ __align__(16) float buf[2][32 * 128];   // 32 KB
    __shared__ __align__(16) ull wsm[8][8][32];        // 16 KB
    __shared__ int s_c0[64], s_c1[64], s_b[4];
    __shared__ int s_last;

    if (tid < 64) {
        int t = t0c + tid;
        int a = g_a[m][t], e = g_e[m][t];
        int len = e - a;
        int c0 = a + ((len * ch) >> 2);
        int c1 = a + ((len * (ch + 1)) >> 2);
        s_c0[tid] = c0; s_c1[tid] = c1;
        int rmin = (c1 > c0) ? c0 : 0x7fffffff;
        int rmax = (c1 > c0) ? c1 : 0;
        #pragma unroll
        for (int off = 16; off; off >>= 1) {
            rmin = min(rmin, __shfl_xor_sync(0xffffffffu, rmin, off));
            rmax = max(rmax, __shfl_xor_sync(0xffffffffu, rmax, off));
        }
        if (lane == 0) { s_b[warp * 2] = rmin; s_b[warp * 2 + 1] = rmax; }
    }
    __syncthreads();
    int amin = min(s_b[0], s_b[2]), emax = max(s_b[1], s_b[3]);

    float nitau = -__expf(-(m ? *lt2 : *lt1));       // -1/tau
    int t0 = t0c + warp * 8;                         // 8 queries per warp

    float alpha[8], nbeta[8], dpart[8];
    int aq[8], eq[8];
    ull alo[8], ahi[8];
    int wmin = 0x7fffffff, wmax = 0;
    #pragma unroll
    for (int q = 0; q < 8; q++) {
        int t = t0 + q;
        alpha[q] = g_alpha[m][t]; nbeta[q] = -g_beta[m][t];
        aq[q] = s_c0[warp * 8 + q]; eq[q] = s_c1[warp * 8 + q];
        dpart[q] = 0.f; alo[q] = 0ull; ahi[q] = 0ull;
        if (eq[q] > aq[q]) { wmin = min(wmin, aq[q]); wmax = max(wmax, eq[q]); }
    }

    const float* gV = &g_V[m][0][0];
    const float* kr = g_kraw[m];
    ull* wme = &wsm[warp][0][0];
    unsigned sbuf0 = d_su32(&buf[0][0]);
    unsigned sbuf1 = d_su32(&buf[1][0]);

    int ntiles = (emax > amin) ? ((emax - amin + 31) >> 5) : 0;

    if (ntiles > 0) {
        {
            const float* g = gV + (size_t)amin * 128;
            #pragma unroll
            for (int i = 0; i < 4; i++) {
                int cid = i * 256 + tid;
                asm volatile("cp.async.cg.shared.global [%0], [%1], 16;"
                             :: "r"(sbuf0 + cid * 16), "l"(g + cid * 4) : "memory");
            }
            asm volatile("cp.async.commit_group;" ::: "memory");
        }
        int p = 0;
        for (int it = 0; it < ntiles; it++) {
            int l0 = amin + it * 32;
            asm volatile("cp.async.wait_group 0;" ::: "memory");
            __syncthreads();
            if (it + 1 < ntiles) {
                const float* g = gV + (size_t)(l0 + 32) * 128;
                unsigned sd = p ? sbuf0 : sbuf1;
                #pragma unroll
                for (int i = 0; i < 4; i++) {
                    int cid = i * 256 + tid;
                    asm volatile("cp.async.cg.shared.global [%0], [%1], 16;"
                                 :: "r"(sd + cid * 16), "l"(g + cid * 4) : "memory");
                }
            }
            asm volatile("cp.async.commit_group;" ::: "memory");

            // per-warp tile skip
            if (l0 < wmax && l0 + 32 > wmin) {
                // weight phase: lane = row, 8 queries
                int l = l0 + lane;
                float k = __ldg(kr + l);
                #pragma unroll
                for (int q = 0; q < 8; q++) {
                    float s = fmaf(nbeta[q], k, alpha[q]);
                    float w = (l >= aq[q] && l < eq[q]) ? __expf(s * s * nitau) : 0.f;
                    wme[q * 32 + lane] = d_pk2(w);
                    dpart[q] += w;
                }
                __syncwarp();

                // compute phase: j in pairs, LDS.128 on V and per-query weight pairs
                const ulonglong2* bp = (const ulonglong2*)buf[p];
                #pragma unroll 2
                for (int j2 = 0; j2 < 16; j2++) {
                    ulonglong2 v0 = bp[(2 * j2) * 32 + lane];
                    ulonglong2 v1 = bp[(2 * j2 + 1) * 32 + lane];
                    #pragma unroll
                    for (int q = 0; q < 8; q++) {
                        ulonglong2 wq = *(const ulonglong2*)&wme[q * 32 + 2 * j2];
                        alo[q] = d_fma2(wq.x, v0.x, alo[q]);
                        ahi[q] = d_fma2(wq.x, v0.y, ahi[q]);
                        alo[q] = d_fma2(wq.y, v1.x, alo[q]);
                        ahi[q] = d_fma2(wq.y, v1.y, ahi[q]);
                    }
                }
                __syncwarp();
            }
            p ^= 1;
        }
    }

    #pragma unroll
    for (int q = 0; q < 8; q++)
        #pragma unroll
        for (int off = 16; off; off >>= 1)
            dpart[q] += __shfl_xor_sync(0xffffffffu, dpart[q], off);

    // write partials
    float4* pa = (float4*)g_pacc[ch][m];
    #pragma unroll
    for (int q = 0; q < 8; q++) {
        float2 lo = d_up(alo[q]), hi = d_up(ahi[q]);
        pa[(t0 + q) * 32 + lane] = make_float4(lo.x, lo.y, hi.x, hi.y);
        if (lane == 0) g_pden[ch][m][t0 + q] = dpart[q];
    }

    // last CTA of the (m, qb) group combines all chunks (fixed order -> deterministic)
    __threadfence();
    __syncthreads();
    if (tid == 0) s_last = atomicAdd(&g_cnt[m][qb], 1);
    __syncthreads();
    if (s_last == NCHUNK - 1) {
        float4* out4 = (float4*)out;
        #pragma unroll
        for (int q = 0; q < 8; q++) {
            int t = t0 + q;
            float den = (float)g_nc[m][t];
            float4 acc = make_float4(0.f, 0.f, 0.f, 0.f);
            #pragma unroll
            for (int cc = 0; cc < NCHUNK; cc++) {
                den += g_pden[cc][m][t];
                float4 a0 = ((const float4*)g_pacc[cc][m])[t * 32 + lane];
                acc.x += a0.x; acc.y += a0.y; acc.z += a0.z; acc.w += a0.w;
            }
            float inv = 1.f / den;
            out4[t * 64 + m * 32 + lane] =
                make_float4(acc.x * inv, acc.y * inv, acc.z * inv, acc.w * inv);
        }
    }
}

// ---------------- launch ----------------
extern "C" void kernel_launch(void* const* d_in, const int* in_sizes, int n_in,
                              void* d_out, int out_size)
{
    int RD, RT, RI, M1D, M1T, M1I, M2D, M2T, M2I, WQ, BQ, WK1, BK1, WV1, BV1, WK2, BK2, WV2, BV2, LT1, LT2;
    if (in_sizes[3] == 4096 * 130) {
        RD=0; RT=1; RI=2; M1D=3; M1T=4; M1I=5; M2D=6; M2T=7; M2I=8;
        WQ=9; BQ=10; WK1=11; BK1=12; WV1=13; BV1=14; WK2=15; BK2=16; WV2=17; BV2=18; LT1=19; LT2=20;
    } else {
        RD=0; RT=1; M1D=2; M1T=3; M2D=4; M2T=5;
        WQ=6; BQ=7; WK1=8; BK1=9; WV1=10; BV1=11; WK2=12; BK2=13; WV2=14; BV2=15;
        LT1=16; LT2=17; RI=18; M1I=19; M2I=20;
    }

    k_pre<<<NQB + 256, 512>>>(
        (const float*)d_in[RD], (const float*)d_in[RT], (const int*)d_in[RI],
        (const float*)d_in[M1D], (const float*)d_in[M1T], (const int*)d_in[M1I],
        (const float*)d_in[M2D], (const float*)d_in[M2T], (const int*)d_in[M2I],
        (const float*)d_in[WQ], (const float*)d_in[BQ],
        (const float*)d_in[WK1], (const float*)d_in[BK1],
        (const float*)d_in[WV1], (const float*)d_in[BV1],
        (const float*)d_in[WK2], (const float*)d_in[BK2],
        (const float*)d_in[WV2], (const float*)d_in[BV2]);

    k_attn<<<dim3(64, 2, NCHUNK), 256>>>(
        (const float*)d_in[LT1], (const float*)d_in[LT2], (float*)d_out);
}

// round 13
// speedup vs baseline: 1.5140x; 1.5140x over previous
#include <cuda_runtime.h>
#include <cuda_bf16.h>

#define T_Q 4096
#define L_KV 4096
#define LPAD (L_KV + 32)
#define NQB 64
#define NCHUNK 4

typedef unsigned long long ull;

// ---------------- scratch ----------------
__device__ __nv_bfloat16 g_Vh[2][LPAD][128];
__device__ __nv_bfloat16 g_Vl[2][LPAD][128];
__device__ float g_kraw[2][LPAD];
__device__ float g_alpha[2][T_Q];
__device__ float g_beta[2][T_Q];
__device__ int   g_a[2][T_Q];
__device__ int   g_e[2][T_Q];
__device__ int   g_nc[2][T_Q];
__device__ float g_pacc[NCHUNK][2][T_Q][128];
__device__ float g_pden[NCHUNK][2][T_Q];
__device__ int   g_cnt[2][128];

// ---------------- helpers ----------------
__device__ __forceinline__ ull d_pk2(float a) {
    ull r; asm("mov.b64 %0, {%1, %1};" : "=l"(r) : "f"(a)); return r;
}
__device__ __forceinline__ ull d_fma2(ull a, ull b, ull c) {
    ull d; asm("fma.rn.f32x2 %0, %1, %2, %3;" : "=l"(d) : "l"(a), "l"(b), "l"(c)); return d;
}
__device__ __forceinline__ float2 d_up(ull v) {
    float2 f; asm("mov.b64 {%0, %1}, %2;" : "=f"(f.x), "=f"(f.y) : "l"(v)); return f;
}
__device__ __forceinline__ unsigned d_su32(const void* p) {
    unsigned r;
    asm("{ .reg .u64 t; cvta.to.shared.u64 t, %1; cvt.u32.u64 %0, t; }" : "=r"(r) : "l"(p));
    return r;
}
__device__ __forceinline__ void d_ldsm_x4(unsigned addr, unsigned& r0, unsigned& r1,
                                          unsigned& r2, unsigned& r3) {
    asm volatile("ldmatrix.sync.aligned.m8n8.x4.shared.b16 {%0,%1,%2,%3}, [%4];"
                 : "=r"(r0), "=r"(r1), "=r"(r2), "=r"(r3) : "r"(addr));
}
__device__ __forceinline__ void d_ldsm_x2t(unsigned addr, unsigned& r0, unsigned& r1) {
    asm volatile("ldmatrix.sync.aligned.m8n8.x2.trans.shared.b16 {%0,%1}, [%2];"
                 : "=r"(r0), "=r"(r1) : "r"(addr));
}
__device__ __forceinline__ void d_mma(float* d, const unsigned* a, const unsigned* b) {
    asm volatile("mma.sync.aligned.m16n8k16.row.col.f32.bf16.bf16.f32 "
                 "{%0,%1,%2,%3}, {%4,%5,%6,%7}, {%8,%9}, {%0,%1,%2,%3};"
                 : "+f"(d[0]), "+f"(d[1]), "+f"(d[2]), "+f"(d[3])
                 : "r"(a[0]), "r"(a[1]), "r"(a[2]), "r"(a[3]), "r"(b[0]), "r"(b[1]));
}
__device__ __forceinline__ void d_split_store(float4 o, __nv_bfloat16* hp, __nv_bfloat16* lp) {
    float v[4] = {o.x, o.y, o.z, o.w};
    __nv_bfloat16 h[4], l[4];
    #pragma unroll
    for (int i = 0; i < 4; i++) {
        h[i] = __float2bfloat16(v[i]);
        l[i] = __float2bfloat16(v[i] - __bfloat162float(h[i]));
    }
    ((__nv_bfloat162*)hp)[0] = __halves2bfloat162(h[0], h[1]);
    ((__nv_bfloat162*)hp)[1] = __halves2bfloat162(h[2], h[3]);
    ((__nv_bfloat162*)lp)[0] = __halves2bfloat162(l[0], l[1]);
    ((__nv_bfloat162*)lp)[1] = __halves2bfloat162(l[2], l[3]);
}

// ---------------- templated vproj core: 32 rows/CTA, warp owns 2 rows ----------------
template<int K, int SST>
__device__ __forceinline__ void vproj_core(const float* __restrict__ sm, int tid, int m, int rb,
                                           const float* __restrict__ Wv, const float* __restrict__ bv)
{
    int w = tid >> 5, lane = tid & 31;
    const ulonglong2* Wvp = (const ulonglong2*)Wv;
    float4 bias = ((const float4*)bv)[lane];
    const float* rbase = sm + (w * 2) * SST;

    ull a00 = 0ull, a01 = 0ull, a10 = 0ull, a11 = 0ull;

    #pragma unroll 8
    for (int i4 = 0; i4 < K / 4; i4++) {
        float4 r0 = *(const float4*)(rbase + i4 * 4);
        float4 r1 = *(const float4*)(rbase + SST + i4 * 4);
        #pragma unroll
        for (int ii = 0; ii < 4; ii++) {
            ulonglong2 wv = Wvp[(i4 * 4 + ii) * 32 + lane];
            float s0 = (ii == 0) ? r0.x : (ii == 1) ? r0.y : (ii == 2) ? r0.z : r0.w;
            float s1 = (ii == 0) ? r1.x : (ii == 1) ? r1.y : (ii == 2) ? r1.z : r1.w;
            ull p0 = d_pk2(s0), p1 = d_pk2(s1);
            a00 = d_fma2(p0, wv.x, a00); a01 = d_fma2(p0, wv.y, a01);
            a10 = d_fma2(p1, wv.x, a10); a11 = d_fma2(p1, wv.y, a11);
        }
    }

    int r0i = rb * 32 + w * 2;
    {
        float2 lo = d_up(a00), hi = d_up(a01);
        float4 o = make_float4(lo.x + bias.x, lo.y + bias.y, hi.x + bias.z, hi.y + bias.w);
        d_split_store(o, &g_Vh[m][r0i][4 * lane], &g_Vl[m][r0i][4 * lane]);
    }
    {
        float2 lo = d_up(a10), hi = d_up(a11);
        float4 o = make_float4(lo.x + bias.x, lo.y + bias.y, hi.x + bias.z, hi.y + bias.w);
        d_split_store(o, &g_Vh[m][r0i + 1][4 * lane], &g_Vl[m][r0i + 1][4 * lane]);
    }
    if (lane < 2) g_kraw[m][r0i + lane] = sm[(w * 2 + lane) * SST + (K + 2) - 1];
}

// ---------------- kernel 1: qparams + vproj (structure unchanged from R11) ----------------
__global__ void __launch_bounds__(512) k_pre(
    const float* __restrict__ ref_data, const float* __restrict__ ref_time,
    const int* __restrict__ ref_idx,
    const float* __restrict__ m1_data, const float* __restrict__ m1_time, const int* __restrict__ m1_idx,
    const float* __restrict__ m2_data, const float* __restrict__ m2_time, const int* __restrict__ m2_idx,
    const float* __restrict__ Wq, const float* __restrict__ bq,
    const float* __restrict__ Wk1, const float* __restrict__ bk1,
    const float* __restrict__ Wv1, const float* __restrict__ bv1,
    const float* __restrict__ Wk2, const float* __restrict__ bk2,
    const float* __restrict__ Wv2, const float* __restrict__ bv2)
{
    __shared__ __align__(16) float sm[4448];     // 17.8 KB, unioned
    int b = blockIdx.x;
    int tid = threadIdx.x;
    int warp = tid >> 5, lane = tid & 31;

    if (b < NQB) {
        float* rbuf = sm;                 // [64][65]
        float* swA  = sm + 4160;          // [2][64]
        float* swB  = swA + 128;          // [2][64]
        float* scAB = swB + 128;          // [4]
        int*   slb  = (int*)(scAB + 4);   // [2][9]

        int t0 = b * 64;
        for (int i = tid; i < 64 * 64; i += 512) {
            int row = i >> 6, col = i & 63;
            rbuf[row * 65 + col] = ref_data[t0 * 64 + i];
        }

        #pragma unroll
        for (int oo = 0; oo < 8; oo++) {
            int o = warp * 8 + oo;        // 0..127
            int m = o >> 6, j = o & 63;
            const float* Wk = m ? Wk2 : Wk1;
            const float* bk = m ? bk2 : bk1;
            const float* wqrow = Wq + j * 128;
            float aA = 0.f, aB = 0.f;
            #pragma unroll
            for (int kk = 0; kk < 4; kk++) {
                int i = lane + 32 * kk;
                if (i < 127) {
                    float w = __ldg(wqrow + i + 1);
                    aA += w * __ldg(bk + i);
                    aB += w * __ldg(Wk + i);
                }
            }
            #pragma unroll
            for (int off = 16; off; off >>= 1) {
                aA += __shfl_xor_sync(0xffffffffu, aA, off);
                aB += __shfl_xor_sync(0xffffffffu, aB, off);
            }
            if (lane == 0) {
                swA[m * 64 + j] = __ldg(wqrow) - aA;
                swB[m * 64 + j] = aB;
            }
        }
        if (warp < 4) {
            int m = warp & 1; bool isB = warp >= 2;
            const float* Wk = m ? Wk2 : Wk1;
            const float* bk = m ? bk2 : bk1;
            const float* vec = isB ? Wk : bk;
            float acc = 0.f;
            #pragma unroll
            for (int kk = 0; kk < 4; kk++) {
                int i = lane + 32 * kk;
                if (i < 127) acc += __ldg(bq + i + 1) * __ldg(vec + i);
            }
            #pragma unroll
            for (int off = 16; off; off >>= 1)
                acc += __shfl_xor_sync(0xffffffffu, acc, off);
            if (lane == 0)
                scAB[warp] = isB ? (acc + __ldg(Wk + 127)) : (__ldg(bq) - acc - __ldg(bk + 127));
        }
        if (warp == 15 && lane < 18) {
            int m = lane / 9, g = lane % 9;
            const int* midx = m ? m2_idx : m1_idx;
            int lo = 0, hi = L_KV;
            while (lo < hi) {
                int md = (lo + hi) >> 1;
                if (midx[md] < g) lo = md + 1; else hi = md;
            }
            slb[m * 9 + g] = lo;
        }
        __syncthreads();

        if (tid < 128) {
            int m = tid >> 6, q = tid & 63;
            int t = t0 + q;
            float dA = 0.f, dB = 0.f;
            #pragma unroll 8
            for (int i = 0; i < 64; i++) {
                float r = rbuf[q * 65 + i];
                dA += r * swA[m * 64 + i];
                dB += r * swB[m * 64 + i];
            }
            g_alpha[m][t] = dA + scAB[m];
            g_beta[m][t]  = dB + scAB[2 + m];

            int id = ref_idx[t];
            float qt = ref_time[t];
            const float* mt = m ? m2_time : m1_time;
            int lo = 0, hi = L_KV;
            while (lo < hi) {
                int md = (lo + hi) >> 1;
                if (mt[md] <= qt) lo = md + 1; else hi = md;
            }
            int a = slb[m * 9 + id], bb = slb[m * 9 + id + 1];
            if (a == bb) { a = 0; bb = L_KV; }
            int e = min(bb, max(lo, a));
            g_a[m][t] = a; g_e[m][t] = e; g_nc[m][t] = bb - e;
        }
        return;
    }

    // ---- vproj path: 32 rows per CTA, 16 warps ----
    int vb = b - NQB;            // 0..255
    int m = vb >> 7;
    int rb = vb & 127;
    int stride = m ? 66 : 130;
    int SST    = m ? 68 : 132;
    const float* src = (m ? m2_data : m1_data) + rb * 32 * stride;

    for (int r = warp; r < 32; r += 16)
        for (int c = lane; c < stride; c += 32)
            sm[r * SST + c] = src[r * stride + c];

    if (vb == 0) {
        for (int i = tid; i < 2 * 32 * 64; i += 512) {
            int mm = i / (32 * 64);
            int r  = i - mm * 32 * 64;      // uint index within padded region
            ((unsigned*)&g_Vh[mm][L_KV][0])[r] = 0u;
            ((unsigned*)&g_Vl[mm][L_KV][0])[r] = 0u;
        }
        if (tid < 64) g_kraw[tid >> 5][L_KV + (tid & 31)] = 0.f;
        if (tid < 256) ((int*)g_cnt)[tid] = 0;
    }
    __syncthreads();

    if (m == 0) vproj_core<128, 132>(sm, tid, 0, rb, Wv1, bv1);
    else        vproj_core<64,  68>(sm, tid, 1, rb, Wv2, bv2);
}

// ---------------- kernel 2: attention via bf16 3-split tensor-core PV ----------------
// CTA = 8 warps, 32 queries. Weight phase (fp32, exact denominators) identical to R11:
// warp w computes rows w*4..w*4+3, lane = kv. Then all warps mma their 16-dim slice.
__global__ void __launch_bounds__(256) k_attn(const float* __restrict__ lt1,
                                              const float* __restrict__ lt2,
                                              float* __restrict__ out)
{
    int m = blockIdx.y, ch = blockIdx.z;
    int c = blockIdx.x;                              // 0..127
    int qb = (c & 1) ? (127 - (c >> 1)) : (c >> 1);  // front/back pairing for balance
    int tid = threadIdx.x;
    int warp = tid >> 5, lane = tid & 31;
    int t0c = qb * 32;

    __shared__ __align__(16) __nv_bfloat16 vh_s[2][32 * 136];   // 17 KB
    __shared__ __align__(16) __nv_bfloat16 vl_s[2][32 * 136];   // 17 KB
    __shared__ __align__(16) __nv_bfloat16 wh_s[32 * 40];       // 2.5 KB
    __shared__ __align__(16) __nv_bfloat16 wl_s[32 * 40];       // 2.5 KB
    __shared__ int s_c0[32], s_c1[32], s_b[2];
    __shared__ int s_last;

    if (tid < 32) {
        int t = t0c + tid;
        int a = g_a[m][t], e = g_e[m][t];
        int len = e - a;
        int c0 = a + ((len * ch) >> 2);
        int c1 = a + ((len * (ch + 1)) >> 2);
        s_c0[tid] = c0; s_c1[tid] = c1;
        int rmin = (c1 > c0) ? c0 : 0x7fffffff;
        int rmax = (c1 > c0) ? c1 : 0;
        #pragma unroll
        for (int off = 16; off; off >>= 1) {
            rmin = min(rmin, __shfl_xor_sync(0xffffffffu, rmin, off));
            rmax = max(rmax, __shfl_xor_sync(0xffffffffu, rmax, off));
        }
        if (tid == 0) { s_b[0] = rmin; s_b[1] = rmax; }
    }
    __syncthreads();
    int amin = s_b[0], emax = s_b[1];

    float nitau = -__expf(-(m ? *lt2 : *lt1));       // -1/tau
    int t0p = t0c + warp * 4;                        // weight-phase query ownership

    float alpha[4], nbeta[4], dpart[4];
    int aq[4], eq[4];
    #pragma unroll
    for (int q = 0; q < 4; q++) {
        int t = t0p + q;
        alpha[q] = g_alpha[m][t]; nbeta[q] = -g_beta[m][t];
        aq[q] = s_c0[warp * 4 + q]; eq[q] = s_c1[warp * 4 + q];
        dpart[q] = 0.f;
    }

    float acc[2][2][4];
    #pragma unroll
    for (int m0 = 0; m0 < 2; m0++)
        #pragma unroll
        for (int n0 = 0; n0 < 2; n0++)
            #pragma unroll
            for (int r = 0; r < 4; r++) acc[m0][n0][r] = 0.f;

    const __nv_bfloat16* gVh = &g_Vh[m][0][0];
    const __nv_bfloat16* gVl = &g_Vl[m][0][0];
    const float* kr = g_kraw[m];
    unsigned svh[2] = { d_su32(&vh_s[0][0]), d_su32(&vh_s[1][0]) };
    unsigned svl[2] = { d_su32(&vl_s[0][0]), d_su32(&vl_s[1][0]) };
    unsigned swh = d_su32(wh_s), swl = d_su32(wl_s);
    int lane15 = lane & 15;

    int ntiles = (emax > amin) ? ((emax - amin + 31) >> 5) : 0;

    if (ntiles > 0) {
        {   // prologue: fill buffer 0 (both hi and lo tiles)
            #pragma unroll
            for (int i = 0; i < 4; i++) {
                int cid = i * 256 + tid;          // 0..1023
                int arr = cid >> 9, cc = cid & 511;
                int kv = cc >> 4, seg = cc & 15;
                const __nv_bfloat16* src = (arr ? gVl : gVh) + (size_t)(amin + kv) * 128 + seg * 8;
                unsigned dst = (arr ? svl[0] : svh[0]) + kv * 272 + seg * 16;
                asm volatile("cp.async.cg.shared.global [%0], [%1], 16;"
                             :: "r"(dst), "l"(src) : "memory");
            }
            asm volatile("cp.async.commit_group;" ::: "memory");
        }
        int p = 0;
        for (int it = 0; it < ntiles; it++) {
            int l0 = amin + it * 32;
            asm volatile("cp.async.wait_group 0;" ::: "memory");
            __syncthreads();                       // V[p] ready; prior mma done with W
            if (it + 1 < ntiles) {
                int lnext = l0 + 32;
                #pragma unroll
                for (int i = 0; i < 4; i++) {
                    int cid = i * 256 + tid;
                    int arr = cid >> 9, cc = cid & 511;
                    int kv = cc >> 4, seg = cc & 15;
                    const __nv_bfloat16* src = (arr ? gVl : gVh) + (size_t)(lnext + kv) * 128 + seg * 8;
                    unsigned dst = (arr ? svl[p ^ 1] : svh[p ^ 1]) + kv * 272 + seg * 16;
                    asm volatile("cp.async.cg.shared.global [%0], [%1], 16;"
                                 :: "r"(dst), "l"(src) : "memory");
                }
            }
            asm volatile("cp.async.commit_group;" ::: "memory");

            // weight phase: fp32 exact, then bf16 split into smem
            {
                int l = l0 + lane;
                float k = __ldg(kr + l);
                #pragma unroll
                for (int q = 0; q < 4; q++) {
                    float s = fmaf(nbeta[q], k, alpha[q]);
                    float w = (l >= aq[q] && l < eq[q]) ? __expf(s * s * nitau) : 0.f;
                    dpart[q] += w;
                    __nv_bfloat16 hb = __float2bfloat16(w);
                    __nv_bfloat16 lb = __float2bfloat16(w - __bfloat162float(hb));
                    int row = warp * 4 + q;
                    wh_s[row * 40 + lane] = hb;
                    wl_s[row * 40 + lane] = lb;
                }
            }
            __syncthreads();                       // W ready

            // mma phase: warp covers dims [warp*16, warp*16+16)
            {
                unsigned bh[8], bl[8];
                #pragma unroll
                for (int k0 = 0; k0 < 2; k0++)
                    #pragma unroll
                    for (int n0 = 0; n0 < 2; n0++) {
                        unsigned off = (unsigned)(((k0 * 16 + lane15) * 136 + warp * 16 + n0 * 8) * 2);
                        int idx = (k0 * 2 + n0) * 2;
                        d_ldsm_x2t(svh[p] + off, bh[idx], bh[idx + 1]);
                        d_ldsm_x2t(svl[p] + off, bl[idx], bl[idx + 1]);
                    }
                #pragma unroll
                for (int m0 = 0; m0 < 2; m0++) {
                    unsigned ah[8], al[8];
                    #pragma unroll
                    for (int k0 = 0; k0 < 2; k0++) {
                        unsigned off = (unsigned)(((m0 * 16 + lane15) * 40 + k0 * 16 + (lane >> 4) * 8) * 2);
                        d_ldsm_x4(swh + off, ah[4 * k0], ah[4 * k0 + 1], ah[4 * k0 + 2], ah[4 * k0 + 3]);
                        d_ldsm_x4(swl + off, al[4 * k0], al[4 * k0 + 1], al[4 * k0 + 2], al[4 * k0 + 3]);
                    }
                    #pragma unroll
                    for (int n0 = 0; n0 < 2; n0++) {
                        float* a = acc[m0][n0];
                        #pragma unroll
                        for (int k0 = 0; k0 < 2; k0++) {
                            int bi = (k0 * 2 + n0) * 2;
                            d_mma(a, ah + 4 * k0, bh + bi);
                            d_mma(a, ah + 4 * k0, bl + bi);
                            d_mma(a, al + 4 * k0, bh + bi);
                        }
                    }
                }
            }
            p ^= 1;
        }
    }

    // denominators (exact fp32)
    #pragma unroll
    for (int q = 0; q < 4; q++)
        #pragma unroll
        for (int off = 16; off; off >>= 1)
            dpart[q] += __shfl_xor_sync(0xffffffffu, dpart[q], off);
    #pragma unroll
    for (int q = 0; q < 4; q++)
        if (lane == 0) g_pden[ch][m][t0p + q] = dpart[q];

    // write numerator partials from mma fragments
    #pragma unroll
    for (int m0 = 0; m0 < 2; m0++)
        #pragma unroll
        for (int n0 = 0; n0 < 2; n0++) {
            int row = t0c + m0 * 16 + (lane >> 2);
            int col = warp * 16 + n0 * 8 + 2 * (lane & 3);
            *(float2*)&g_pacc[ch][m][row][col]     = make_float2(acc[m0][n0][0], acc[m0][n0][1]);
            *(float2*)&g_pacc[ch][m][row + 8][col] = make_float2(acc[m0][n0][2], acc[m0][n0][3]);
        }

    // last CTA of the (m, qb) group combines all chunks (fixed order -> deterministic)
    __threadfence();
    __syncthreads();
    if (tid == 0) s_last = atomicAdd(&g_cnt[m][qb], 1);
    __syncthreads();
    if (s_last == NCHUNK - 1) {
        float4* out4 = (float4*)out;
        #pragma unroll
        for (int q = 0; q < 4; q++) {
            int t = t0p + q;
            float den = (float)g_nc[m][t];
            float4 a4 = make_float4(0.f, 0.f, 0.f, 0.f);
            #pragma unroll
            for (int cc = 0; cc < NCHUNK; cc++) {
                den += g_pden[cc][m][t];
                float4 a0 = ((const float4*)g_pacc[cc][m])[t * 32 + lane];
                a4.x += a0.x; a4.y += a0.y; a4.z += a0.z; a4.w += a0.w;
            }
            float inv = 1.f / den;
            out4[t * 64 + m * 32 + lane] =
                make_float4(a4.x * inv, a4.y * inv, a4.z * inv, a4.w * inv);
        }
    }
}

// ---------------- launch ----------------
extern "C" void kernel_launch(void* const* d_in, const int* in_sizes, int n_in,
                              void* d_out, int out_size)
{
    int RD, RT, RI, M1D, M1T, M1I, M2D, M2T, M2I, WQ, BQ, WK1, BK1, WV1, BV1, WK2, BK2, WV2, BV2, LT1, LT2;
    if (in_sizes[3] == 4096 * 130) {
        RD=0; RT=1; RI=2; M1D=3; M1T=4; M1I=5; M2D=6; M2T=7; M2I=8;
        WQ=9; BQ=10; WK1=11; BK1=12; WV1=13; BV1=14; WK2=15; BK2=16; WV2=17; BV2=18; LT1=19; LT2=20;
    } else {
        RD=0; RT=1; M1D=2; M1T=3; M2D=4; M2T=5;
        WQ=6; BQ=7; WK1=8; BK1=9; WV1=10; BV1=11; WK2=12; BK2=13; WV2=14; BV2=15;
        LT1=16; LT2=17; RI=18; M1I=19; M2I=20;
    }

    k_pre<<<NQB + 256, 512>>>(
        (const float*)d_in[RD], (const float*)d_in[RT], (const int*)d_in[RI],
        (const float*)d_in[M1D], (const float*)d_in[M1T], (const int*)d_in[M1I],
        (const float*)d_in[M2D], (const float*)d_in[M2T], (const int*)d_in[M2I],
        (const float*)d_in[WQ], (const float*)d_in[BQ],
        (const float*)d_in[WK1], (const float*)d_in[BK1],
        (const float*)d_in[WV1], (const float*)d_in[BV1],
        (const float*)d_in[WK2], (const float*)d_in[BK2],
        (const float*)d_in[WV2], (const float*)d_in[BV2]);

    k_attn<<<dim3(128, 2, NCHUNK), 256>>>(
        (const float*)d_in[LT1], (const float*)d_in[LT2], (float*)d_out);
}